// round 15
// baseline (speedup 1.0000x reference)
#include <cuda_runtime.h>
#include <cuda_bf16.h>
#include <math_constants.h>
#include <cstdint>

#if defined(__CUDA_ARCH_FEAT_SM103_ALL) || defined(__CUDA_ARCH_FEAT_SM100_ALL)
#define TC_OK 1
#elif defined(__CUDA_ARCH_SPECIFIC__) && (__CUDA_ARCH_SPECIFIC__ == 1030)
#define TC_OK 1
#elif defined(__CUDA_ARCH_FAMILY_SPECIFIC__) && (__CUDA_ARCH_FAMILY_SPECIFIC__ == 1030)
#define TC_OK 1
#else
#define TC_OK 0
#endif

#define N_PTS 8192
#define DIM   128
#define NTILE 64
#define TILE_BYTES 65536
#define NTHREADS 288

#define BM    64
#define BN    128
#define NTILES_FB (N_PTS / BN)

__device__ __align__(256) unsigned char g_tf[NTILE * TILE_BYTES];
__device__ __align__(256) unsigned int  g_aux[NTILE * 256];
__device__ float g_sq[N_PTS];
__device__ int   g_lab[N_PTS];
__device__ float g_wp[2 * N_PTS];
__device__ float g_wn[2 * N_PTS];
__device__ float g_hp[N_PTS];
__device__ float g_hn[N_PTS];

#define A_OFF      0
#define B_OFF(s)   (65536 + (s) * 65536)
#define AUX_OFF    196608
#define TMEMPTR_OFF 229376
#define MB_A       229384
#define MB_F(s)    (229392 + (s) * 8)
#define MB_D(s)    (229408 + (s) * 8)
#define MB_E(s)    (229440 + (s) * 8)
#define SMEM_TOTAL 229632

#define IDESC_TF32 0x8200910u

typedef unsigned long long u64;

__device__ __forceinline__ uint32_t smem_u32(const void* p) {
    uint32_t a;
    asm("{ .reg .u64 t; cvta.to.shared.u64 t, %1; cvt.u32.u64 %0, t; }" : "=r"(a) : "l"(p));
    return a;
}

#if TC_OK
__device__ __forceinline__ void mbar_init(uint32_t m, uint32_t c) {
    asm volatile("mbarrier.init.shared.b64 [%0], %1;" :: "r"(m), "r"(c) : "memory");
}
__device__ __forceinline__ void mbar_expect(uint32_t m, uint32_t bytes) {
    asm volatile("mbarrier.arrive.expect_tx.shared.b64 _, [%0], %1;" :: "r"(m), "r"(bytes) : "memory");
}
__device__ __forceinline__ void mbar_arrive(uint32_t m) {
    asm volatile("mbarrier.arrive.shared.b64 _, [%0];" :: "r"(m) : "memory");
}
__device__ __forceinline__ void mbar_wait(uint32_t m, uint32_t ph) {
    asm volatile(
        "{\n\t.reg .pred P1;\n\t"
        "LAB_W%=:\n\t"
        "mbarrier.try_wait.parity.acquire.cta.shared::cta.b64 P1, [%0], %1, 0x989680;\n\t"
        "@P1 bra LAB_D%=;\n\t"
        "bra LAB_W%=;\n\t"
        "LAB_D%=:\n\t}"
        :: "r"(m), "r"(ph) : "memory");
}
__device__ __forceinline__ void bulk_cp(uint32_t dst, const void* src, uint32_t bytes, uint32_t mbar) {
    asm volatile(
        "cp.async.bulk.shared::cluster.global.mbarrier::complete_tx::bytes [%0], [%1], %2, [%3];"
        :: "r"(dst), "l"(src), "r"(bytes), "r"(mbar) : "memory");
}
__device__ __forceinline__ void mma_tf32(uint32_t d, uint64_t a, uint64_t b, uint32_t en) {
    asm volatile(
        "{\n\t.reg .pred p;\n\t"
        "setp.ne.u32 p, %5, 0;\n\t"
        "tcgen05.mma.cta_group::1.kind::tf32 [%0], %1, %2, %3, {%4, %4, %4, %4}, p;\n\t"
        "}"
        :: "r"(d), "l"(a), "l"(b), "r"(IDESC_TF32), "r"(0u), "r"(en) : "memory");
}
__device__ __forceinline__ void tc_commit(uint32_t mbar) {
    asm volatile(
        "tcgen05.commit.cta_group::1.mbarrier::arrive::one.shared::cluster.b64 [%0];"
        :: "r"(mbar) : "memory");
}
__device__ __forceinline__ uint64_t make_desc(uint32_t addr) {
    return (uint64_t(2) << 61) | (uint64_t(1) << 46) | (uint64_t(64) << 32) |
           (uint64_t(1) << 16) | ((uint64_t)(addr >> 4) & 0x3FFF);
}
#define TC_FENCE_AFTER()  asm volatile("tcgen05.fence::after_thread_sync;" ::: "memory")
#define TC_FENCE_BEFORE() asm volatile("tcgen05.fence::before_thread_sync;" ::: "memory")
#define TC_WAIT_LD()      asm volatile("tcgen05.wait::ld.sync.aligned;" ::: "memory")

#define LDTM_X32(r, addr) \
    asm volatile( \
        "tcgen05.ld.sync.aligned.32x32b.x32.b32 " \
        "{%0, %1, %2, %3, %4, %5, %6, %7, " \
        " %8, %9, %10, %11, %12, %13, %14, %15, " \
        " %16, %17, %18, %19, %20, %21, %22, %23, " \
        " %24, %25, %26, %27, %28, %29, %30, %31}, [%32];" \
        : "=r"((r)[0]),  "=r"((r)[1]),  "=r"((r)[2]),  "=r"((r)[3]), \
          "=r"((r)[4]),  "=r"((r)[5]),  "=r"((r)[6]),  "=r"((r)[7]), \
          "=r"((r)[8]),  "=r"((r)[9]),  "=r"((r)[10]), "=r"((r)[11]), \
          "=r"((r)[12]), "=r"((r)[13]), "=r"((r)[14]), "=r"((r)[15]), \
          "=r"((r)[16]), "=r"((r)[17]), "=r"((r)[18]), "=r"((r)[19]), \
          "=r"((r)[20]), "=r"((r)[21]), "=r"((r)[22]), "=r"((r)[23]), \
          "=r"((r)[24]), "=r"((r)[25]), "=r"((r)[26]), "=r"((r)[27]), \
          "=r"((r)[28]), "=r"((r)[29]), "=r"((r)[30]), "=r"((r)[31]) \
        : "r"(addr))
#else
__device__ __forceinline__ u64 pkfma(u64 a, u64 b, u64 c) {
    u64 d;
    asm("fma.rn.f32x2 %0, %1, %2, %3;" : "=l"(d) : "l"(a), "l"(b), "l"(c));
    return d;
}
__device__ __forceinline__ float2 unpk(u64 v) {
    float2 r;
    asm("mov.b64 {%0, %1}, %2;" : "=f"(r.x), "=f"(r.y) : "l"(v));
    return r;
}
#endif

// ---------------------------------------------------------------------------
__global__ void prep_kernel(const float* __restrict__ emb, const int* __restrict__ lab32) {
    int gtid = blockIdx.x * blockDim.x + threadIdx.x;
    int r = gtid >> 5, lane = gtid & 31;

    const float4 v = ((const float4*)(emb + (size_t)r * DIM))[lane];
    float s = v.x * v.x + v.y * v.y + v.z * v.z + v.w * v.w;
    #pragma unroll
    for (int o = 16; o; o >>= 1) s += __shfl_xor_sync(0xffffffffu, s, o);

    uint4 pk;
    asm("cvt.rna.tf32.f32 %0, %1;" : "=r"(pk.x) : "f"(v.x));
    asm("cvt.rna.tf32.f32 %0, %1;" : "=r"(pk.y) : "f"(v.y));
    asm("cvt.rna.tf32.f32 %0, %1;" : "=r"(pk.z) : "f"(v.z));
    asm("cvt.rna.tf32.f32 %0, %1;" : "=r"(pk.w) : "f"(v.w));

    int tile = r >> 7;
    int rin  = r & 127;
    int k0   = lane * 4;
    uint32_t byte_off = (uint32_t)(((rin >> 3) + (k0 >> 5) * 16) * 1024 + (rin & 7) * 128 + (k0 & 31) * 4);
    uint32_t sw = byte_off ^ ((byte_off >> 3) & 0x70);
    *(uint4*)(g_tf + (size_t)tile * TILE_BYTES + sw) = pk;

    if (lane == 0) {
        g_sq[r] = s;
        g_aux[tile * 256 + 128 + rin] = __float_as_uint(-0.5f * s);
    }

    if (gtid < N_PTS) {
        int odd_or = 0;
        #pragma unroll
        for (int j = 0; j < 16; j++) odd_or |= lab32[2 * j + 1];
        bool is64 = (odd_or == 0);
        int L = is64 ? lab32[2 * gtid] : lab32[gtid];
        g_lab[gtid] = L;
        g_aux[(gtid >> 7) * 256 + (gtid & 127)] = (unsigned)L;
    }
}

// ---------------------------------------------------------------------------
__global__ void __launch_bounds__(NTHREADS, 1) triplet_main(const float* __restrict__ emb) {
#if TC_OK
    extern __shared__ unsigned char smem[];
    const uint32_t sb = smem_u32(smem);
    const int tid = threadIdx.x, wid = tid >> 5, lid = tid & 31;
    const int strip = blockIdx.x >> 1;
    const int half  = blockIdx.x & 1;
    const int tbase = half * 32;

    if (wid == 8) {
        asm volatile("tcgen05.alloc.cta_group::1.sync.aligned.shared::cta.b32 [%0], %1;"
                     :: "r"(sb + TMEMPTR_OFF), "r"(512u) : "memory");
        asm volatile("tcgen05.relinquish_alloc_permit.cta_group::1.sync.aligned;");
    }
    if (tid == 0) {
        mbar_init(sb + MB_A, 1);
        mbar_init(sb + MB_F(0), 1); mbar_init(sb + MB_F(1), 1);
        #pragma unroll
        for (int s = 0; s < 4; s++) {
            mbar_init(sb + MB_D(s), 1);
            mbar_init(sb + MB_E(s), 8);
        }
    }
    __syncthreads();
    uint32_t tmem;
    asm volatile("ld.shared.b32 %0, [%1];" : "=r"(tmem) : "r"(sb + TMEMPTR_OFF));

    if (tid == 0) {
        mbar_expect(sb + MB_A, 98304);
        bulk_cp(sb + A_OFF,         g_tf + (size_t)strip * TILE_BYTES,         32768, sb + MB_A);
        bulk_cp(sb + A_OFF + 32768, g_tf + (size_t)strip * TILE_BYTES + 32768, 32768, sb + MB_A);
        bulk_cp(sb + AUX_OFF, (const unsigned char*)g_aux + (size_t)tbase * 1024, 32768, sb + MB_A);
        #pragma unroll
        for (int s = 0; s < 2; s++) {
            uint32_t fb = sb + MB_F(s);
            mbar_expect(fb, 65536);
            bulk_cp(sb + B_OFF(s),         g_tf + (size_t)(tbase + s) * TILE_BYTES,         32768, fb);
            bulk_cp(sb + B_OFF(s) + 32768, g_tf + (size_t)(tbase + s) * TILE_BYTES + 32768, 32768, fb);
        }
    }

    if (wid == 8) {
        if (lid == 0) {
            mbar_wait(sb + MB_A, 0);
            const uint64_t ad = make_desc(sb + A_OFF);
            for (int t = 0; t < 32; t++) {
                const uint32_t st = t & 1;
                const uint32_t db = t & 3;
                mbar_wait(sb + MB_F(st), (t >> 1) & 1);
                if (t >= 4)
                    mbar_wait(sb + MB_E(db), ((t - 4) >> 2) & 1);
                const uint64_t bd = make_desc(sb + B_OFF(st));
                const uint32_t dT = tmem + db * 128;
                #pragma unroll
                for (int s = 0; s < 16; s++) {
                    uint32_t off = (s & 3) * 2 + (s >> 2) * 1024;
                    mma_tf32(dT, ad + off, bd + off, s > 0);
                }
                tc_commit(sb + MB_D(db));
            }
        }
    } else {
        // epilogue warps 0-7: LDTM(t+1) streams under compute(t)
        const int rloc  = (wid & 3) * 32 + lid;
        const int cbase = (wid >> 2) * 64;
        const int L = g_lab[strip * 128 + rloc];
        float wp = CUDART_INF_F;
        float wn = -CUDART_INF_F;

        uint32_t drA[64], drB[64];

        #define COMPUTE_TILE(DR, TT) do {                                       \
            const int*   labs = (const int*)(smem + AUX_OFF + (TT) * 1024);     \
            const float* qs   = (const float*)(smem + AUX_OFF + (TT) * 1024 + 512); \
            if ((tbase + (TT)) != strip) {                                      \
                _Pragma("unroll")                                               \
                for (int i = 0; i < 64; i += 4) {                               \
                    const int j = cbase + i;                                    \
                    int4   lb = *(const int4*)(labs + j);                       \
                    float4 q  = *(const float4*)(qs + j);                       \
                    float w0 = __uint_as_float((DR)[i+0]) + q.x;                \
                    float w1 = __uint_as_float((DR)[i+1]) + q.y;                \
                    float w2 = __uint_as_float((DR)[i+2]) + q.z;                \
                    float w3 = __uint_as_float((DR)[i+3]) + q.w;                \
                    if (lb.x == L) wp = fminf(wp, w0); else wn = fmaxf(wn, w0); \
                    if (lb.y == L) wp = fminf(wp, w1); else wn = fmaxf(wn, w1); \
                    if (lb.z == L) wp = fminf(wp, w2); else wn = fmaxf(wn, w2); \
                    if (lb.w == L) wp = fminf(wp, w3); else wn = fmaxf(wn, w3); \
                }                                                               \
            } else {                                                            \
                _Pragma("unroll")                                               \
                for (int i = 0; i < 64; i += 4) {                               \
                    const int j = cbase + i;                                    \
                    int4   lb = *(const int4*)(labs + j);                       \
                    float4 q  = *(const float4*)(qs + j);                       \
                    float w0 = __uint_as_float((DR)[i+0]) + q.x;                \
                    float w1 = __uint_as_float((DR)[i+1]) + q.y;                \
                    float w2 = __uint_as_float((DR)[i+2]) + q.z;                \
                    float w3 = __uint_as_float((DR)[i+3]) + q.w;                \
                    if (lb.x == L) { if (j+0 != rloc) wp = fminf(wp, w0); } else wn = fmaxf(wn, w0); \
                    if (lb.y == L) { if (j+1 != rloc) wp = fminf(wp, w1); } else wn = fmaxf(wn, w1); \
                    if (lb.z == L) { if (j+2 != rloc) wp = fminf(wp, w2); } else wn = fmaxf(wn, w2); \
                    if (lb.w == L) { if (j+3 != rloc) wp = fminf(wp, w3); } else wn = fmaxf(wn, w3); \
                }                                                               \
            }                                                                   \
        } while (0)

        mbar_wait(sb + MB_D(0), 0);
        TC_FENCE_AFTER();
        LDTM_X32(drA,      tmem + cbase);
        LDTM_X32(drA + 32, tmem + cbase + 32);

        #pragma unroll 1
        for (int t = 0; t < 32; t += 2) {
            TC_WAIT_LD();
            TC_FENCE_BEFORE();
            if (lid == 0) mbar_arrive(sb + MB_E(t & 3));
            if (tid == 0 && t + 2 < 32) {
                const uint32_t fb = sb + MB_F(t & 1);
                mbar_expect(fb, 65536);
                bulk_cp(sb + B_OFF(t & 1),
                        g_tf + (size_t)(tbase + t + 2) * TILE_BYTES, 32768, fb);
                bulk_cp(sb + B_OFF(t & 1) + 32768,
                        g_tf + (size_t)(tbase + t + 2) * TILE_BYTES + 32768, 32768, fb);
            }
            {
                const uint32_t db1 = (t + 1) & 3;
                mbar_wait(sb + MB_D(db1), ((t + 1) >> 2) & 1);
                TC_FENCE_AFTER();
                LDTM_X32(drB,      tmem + db1 * 128 + cbase);
                LDTM_X32(drB + 32, tmem + db1 * 128 + cbase + 32);
            }
            COMPUTE_TILE(drA, t);

            TC_WAIT_LD();
            TC_FENCE_BEFORE();
            if (lid == 0) mbar_arrive(sb + MB_E((t + 1) & 3));
            if (tid == 0 && t + 3 < 32) {
                const uint32_t fb = sb + MB_F((t + 1) & 1);
                mbar_expect(fb, 65536);
                bulk_cp(sb + B_OFF((t + 1) & 1),
                        g_tf + (size_t)(tbase + t + 3) * TILE_BYTES, 32768, fb);
                bulk_cp(sb + B_OFF((t + 1) & 1) + 32768,
                        g_tf + (size_t)(tbase + t + 3) * TILE_BYTES + 32768, 32768, fb);
            }
            if (t + 2 < 32) {
                const uint32_t db2 = (t + 2) & 3;
                mbar_wait(sb + MB_D(db2), ((t + 2) >> 2) & 1);
                TC_FENCE_AFTER();
                LDTM_X32(drA,      tmem + db2 * 128 + cbase);
                LDTM_X32(drA + 32, tmem + db2 * 128 + cbase + 32);
            }
            COMPUTE_TILE(drB, t + 1);
        }
        #undef COMPUTE_TILE

        float* sWP = (float*)smem;
        float* sWN = sWP + 256;
        sWP[(wid >> 2) * 128 + rloc] = wp;
        sWN[(wid >> 2) * 128 + rloc] = wn;
    }

    __syncthreads();
    if (tid < 128) {
        float* sWP = (float*)smem;
        float* sWN = sWP + 256;
        float p = fminf(sWP[tid], sWP[128 + tid]);
        float n = fmaxf(sWN[tid], sWN[128 + tid]);
        g_wp[half * N_PTS + strip * 128 + tid] = p;
        g_wn[half * N_PTS + strip * 128 + tid] = n;
    }
    __syncthreads();
    if (wid == 8) {
        asm volatile("tcgen05.dealloc.cta_group::1.sync.aligned.b32 %0, %1;"
                     :: "r"(tmem), "r"(512u));
    }
#else
    // ===================== FALLBACK: pkFMA kernel (guarded to 256 threads) ====
    extern __shared__ float smemf[];
    if (threadIdx.x < 256) {
    float* As2 = smemf;
    float* BsA = smemf + 16384;
    float* BsB = smemf + 32768;
    float* sSq = smemf + 49152;
    int*   sLb = (int*)(smemf + 49408);

    const int tid  = threadIdx.x;
    const int row0 = blockIdx.x * BM;
    const int tn   = tid & 15;
    const int tm   = tid >> 4;

    {
        int m  = tid & 63;
        int kq = tid >> 6;
        const float* src = emb + (size_t)(row0 + m) * DIM;
        #pragma unroll
        for (int q = 0; q < 8; q++) {
            int k = kq * 32 + q * 4;
            float4 v = *(const float4*)(src + k);
            float x0 = -2.f * v.x, x1 = -2.f * v.y, x2 = -2.f * v.z, x3 = -2.f * v.w;
            As2[(k + 0) * 128 + 2 * m] = x0; As2[(k + 0) * 128 + 2 * m + 1] = x0;
            As2[(k + 1) * 128 + 2 * m] = x1; As2[(k + 1) * 128 + 2 * m + 1] = x1;
            As2[(k + 2) * 128 + 2 * m] = x2; As2[(k + 2) * 128 + 2 * m + 1] = x2;
            As2[(k + 3) * 128 + 2 * m] = x3; As2[(k + 3) * 128 + 2 * m + 1] = x3;
        }
    }

    const int bn = tid & 127;
    const int kh = tid >> 7;
    {
        const float4* src = (const float4*)(emb + (size_t)bn * DIM + kh * 64);
        #pragma unroll
        for (int q = 0; q < 16; q++) {
            float4 v = src[q];
            int k = kh * 64 + q * 4;
            BsA[(k + 0) * 128 + bn] = v.x; BsA[(k + 1) * 128 + bn] = v.y;
            BsA[(k + 2) * 128 + bn] = v.z; BsA[(k + 3) * 128 + bn] = v.w;
        }
        if (tid < 128) { sSq[tid] = g_sq[tid]; sLb[tid] = g_lab[tid]; }
    }
    __syncthreads();

    int myLab[4];
    #pragma unroll
    for (int mi = 0; mi < 4; mi++) myLab[mi] = g_lab[row0 + tm * 4 + mi];

    float posm[4] = {-CUDART_INF_F, -CUDART_INF_F, -CUDART_INF_F, -CUDART_INF_F};
    float negm[4] = { CUDART_INF_F,  CUDART_INF_F,  CUDART_INF_F,  CUDART_INF_F};

    int cur = 0;
    for (int t = 0; t < NTILES_FB; t++) {
        float4 breg[16];
        float sqr = 0.f; int lbr = 0;
        const bool has = (t + 1 < NTILES_FB);
        if (has) {
            int coln = (t + 1) * BN;
            const float4* src = (const float4*)(emb + (size_t)(coln + bn) * DIM + kh * 64);
            #pragma unroll
            for (int q = 0; q < 16; q++) breg[q] = src[q];
            if (tid < 128) { sqr = g_sq[coln + tid]; lbr = g_lab[coln + tid]; }
        }

        const float* Bc = (cur == 0) ? BsA : BsB;
        const float* sS = sSq + cur * 128;
        const int*   sL = sLb + cur * 128;

        u64 acc[16];
        #pragma unroll
        for (int i = 0; i < 16; i++) acc[i] = 0ull;

        const float* aBase  = As2 + tm * 8;
        const float* bBase0 = Bc + tn * 4;
        const float* bBase1 = Bc + 64 + tn * 4;

        #pragma unroll 16
        for (int k = 0; k < DIM; k++) {
            ulonglong2 a01 = *(const ulonglong2*)(aBase  + k * 128);
            ulonglong2 a23 = *(const ulonglong2*)(aBase  + k * 128 + 4);
            ulonglong2 b01 = *(const ulonglong2*)(bBase0 + k * 128);
            ulonglong2 b23 = *(const ulonglong2*)(bBase1 + k * 128);
            acc[ 0] = pkfma(a01.x, b01.x, acc[ 0]);
            acc[ 1] = pkfma(a01.x, b01.y, acc[ 1]);
            acc[ 2] = pkfma(a01.x, b23.x, acc[ 2]);
            acc[ 3] = pkfma(a01.x, b23.y, acc[ 3]);
            acc[ 4] = pkfma(a01.y, b01.x, acc[ 4]);
            acc[ 5] = pkfma(a01.y, b01.y, acc[ 5]);
            acc[ 6] = pkfma(a01.y, b23.x, acc[ 6]);
            acc[ 7] = pkfma(a01.y, b23.y, acc[ 7]);
            acc[ 8] = pkfma(a23.x, b01.x, acc[ 8]);
            acc[ 9] = pkfma(a23.x, b01.y, acc[ 9]);
            acc[10] = pkfma(a23.x, b23.x, acc[10]);
            acc[11] = pkfma(a23.x, b23.y, acc[11]);
            acc[12] = pkfma(a23.y, b01.x, acc[12]);
            acc[13] = pkfma(a23.y, b01.y, acc[13]);
            acc[14] = pkfma(a23.y, b23.x, acc[14]);
            acc[15] = pkfma(a23.y, b23.y, acc[15]);
        }

        float4 sq0 = *(const float4*)(sS + tn * 4);
        float4 sq1 = *(const float4*)(sS + 64 + tn * 4);
        int4   lb0 = *(const int4*)(sL + tn * 4);
        int4   lb1 = *(const int4*)(sL + 64 + tn * 4);
        const int col0 = t * BN;

        #pragma unroll
        for (int mi = 0; mi < 4; mi++) {
            const int gm = row0 + tm * 4 + mi;
            const int L  = myLab[mi];
            float pm = posm[mi], nm = negm[mi];
            float2 v0 = unpk(acc[mi * 4 + 0]);
            float2 v1 = unpk(acc[mi * 4 + 1]);
            float2 v2 = unpk(acc[mi * 4 + 2]);
            float2 v3 = unpk(acc[mi * 4 + 3]);
            #define ELEM(gval, sqv, lbv, nloc) do {                      \
                float v = (sqv) + (gval);                                \
                int gn = col0 + (nloc);                                  \
                if ((lbv) == L) { if (gn != gm) pm = fmaxf(pm, v); }     \
                else            { nm = fminf(nm, v); }                   \
            } while (0)
            ELEM(v0.x, sq0.x, lb0.x, tn * 4 + 0);
            ELEM(v0.y, sq0.y, lb0.y, tn * 4 + 1);
            ELEM(v1.x, sq0.z, lb0.z, tn * 4 + 2);
            ELEM(v1.y, sq0.w, lb0.w, tn * 4 + 3);
            ELEM(v2.x, sq1.x, lb1.x, 64 + tn * 4 + 0);
            ELEM(v2.y, sq1.y, lb1.y, 64 + tn * 4 + 1);
            ELEM(v3.x, sq1.z, lb1.z, 64 + tn * 4 + 2);
            ELEM(v3.y, sq1.w, lb1.w, 64 + tn * 4 + 3);
            #undef ELEM
            posm[mi] = pm; negm[mi] = nm;
        }

        if (has) {
            float* Bd = (cur == 0) ? BsB : BsA;
            #pragma unroll
            for (int q = 0; q < 16; q++) {
                int k = kh * 64 + q * 4;
                Bd[(k + 0) * 128 + bn] = breg[q].x;
                Bd[(k + 1) * 128 + bn] = breg[q].y;
                Bd[(k + 2) * 128 + bn] = breg[q].z;
                Bd[(k + 3) * 128 + bn] = breg[q].w;
            }
            if (tid < 128) { sSq[(cur ^ 1) * 128 + tid] = sqr; sLb[(cur ^ 1) * 128 + tid] = lbr; }
        }
        __syncthreads();
        cur ^= 1;
    }

    float* redP = As2;
    float* redN = As2 + 1024;
    #pragma unroll
    for (int mi = 0; mi < 4; mi++) {
        redP[tn * 64 + tm * 4 + mi] = posm[mi];
        redN[tn * 64 + tm * 4 + mi] = negm[mi];
    }
    __syncthreads();
    if (tid < 64) {
        float p = -CUDART_INF_F, nn = CUDART_INF_F;
        #pragma unroll
        for (int j = 0; j < 16; j++) {
            p  = fmaxf(p,  redP[j * 64 + tid]);
            nn = fminf(nn, redN[j * 64 + tid]);
        }
        float sqi = g_sq[row0 + tid];
        g_hp[row0 + tid] = sqi + p;
        g_hn[row0 + tid] = sqi + nn;
    }
    } // tid < 256
#endif
}

// ---------------------------------------------------------------------------
__global__ void finalize_kernel(float* __restrict__ out) {
    __shared__ float ss[256];
    __shared__ int   sc[256];
    int tid = threadIdx.x;
    float s = 0.f; int c = 0;
    for (int i = tid; i < N_PTS; i += 256) {
#if TC_OK
        float wp = fminf(g_wp[i], g_wp[N_PTS + i]);
        float wn = fmaxf(g_wn[i], g_wn[N_PTS + i]);
        float sq = g_sq[i];
        float hp = fmaf(-2.f, wp, sq);
        float hn = fmaf(-2.f, wn, sq);
#else
        float hp = g_hp[i], hn = g_hn[i];
#endif
        if (!isinf(hp) && !isinf(hn)) {
            float dp = sqrtf(fmaxf(hp, 1e-12f));
            float dn = sqrtf(fmaxf(hn, 1e-12f));
            s += fmaxf(dp - dn + 0.3f, 1e-6f);
            c++;
        }
    }
    ss[tid] = s; sc[tid] = c;
    __syncthreads();
    for (int o = 128; o; o >>= 1) {
        if (tid < o) { ss[tid] += ss[tid + o]; sc[tid] += sc[tid + o]; }
        __syncthreads();
    }
    if (tid == 0) out[0] = sc[0] ? (ss[0] / (float)sc[0]) : 0.f;
}

// ---------------------------------------------------------------------------
extern "C" void kernel_launch(void* const* d_in, const int* in_sizes, int n_in,
                              void* d_out, int out_size) {
    const float* emb = (const float*)d_in[0];
    const int*   lab = (const int*)d_in[1];

    cudaFuncSetAttribute(triplet_main, cudaFuncAttributeMaxDynamicSharedMemorySize, SMEM_TOTAL);

    prep_kernel<<<1024, 256>>>(emb, lab);
    triplet_main<<<128, NTHREADS, SMEM_TOTAL>>>(emb);
    finalize_kernel<<<1, 256>>>((float*)d_out);
}

// round 16
// speedup vs baseline: 1.1509x; 1.1509x over previous
#include <cuda_runtime.h>
#include <cuda_bf16.h>
#include <math_constants.h>
#include <cstdint>

#if defined(__CUDA_ARCH_FEAT_SM103_ALL) || defined(__CUDA_ARCH_FEAT_SM100_ALL)
#define TC_OK 1
#elif defined(__CUDA_ARCH_SPECIFIC__) && (__CUDA_ARCH_SPECIFIC__ == 1030)
#define TC_OK 1
#elif defined(__CUDA_ARCH_FAMILY_SPECIFIC__) && (__CUDA_ARCH_FAMILY_SPECIFIC__ == 1030)
#define TC_OK 1
#else
#define TC_OK 0
#endif

#define N_PTS 8192
#define DIM   128
#define NTILE 64
#define FT_BYTES 65536          // full 128x128 tf32 tile (A operand)
#define HT_BYTES 32768          // half 64x128 tf32 tile (B operand, cg2 split)
#define NTHREADS 288            // 8 epi warps + 1 MMA/GO warp

#define BM    64
#define BN    128
#define NTILES_FB (N_PTS / BN)

__device__ __align__(256) unsigned char g_full[NTILE * FT_BYTES];
__device__ __align__(256) unsigned char g_half[NTILE * 2 * HT_BYTES];
__device__ __align__(256) unsigned int  g_aux[NTILE * 256];
__device__ float g_sq[N_PTS];
__device__ int   g_lab[N_PTS];
__device__ float g_wp[2 * N_PTS];
__device__ float g_wn[2 * N_PTS];
__device__ float g_hp[N_PTS];
__device__ float g_hn[N_PTS];

// ---------------- SMEM layout (bytes) ----------------
#define A_OFF      0                       // 64KB A strip (full tile image)
#define B_OFF(s)   (65536 + (s) * 32768)   // 4 stages x 32KB B half
#define AUX_OFF    196608                  // ALL 32 tiles x 1KB, preloaded once
#define TMEMPTR_OFF 229376
#define MB_A       229384
#define MB_F(s)    (229392 + (s) * 8)
#define MB_D(s)    (229424 + (s) * 8)
#define MB_E(s)    (229456 + (s) * 8)
#define MB_GO(s)   (229488 + (s) * 8)
#define SMEM_TOTAL 229632

// kind::tf32 cg2 idesc: F32 acc, tf32 a/b, N=128, M=256
#define IDESC_TF32_CG2 0x10200910u

typedef unsigned long long u64;

__device__ __forceinline__ uint32_t smem_u32(const void* p) {
    uint32_t a;
    asm("{ .reg .u64 t; cvta.to.shared.u64 t, %1; cvt.u32.u64 %0, t; }" : "=r"(a) : "l"(p));
    return a;
}

#if TC_OK
__device__ __forceinline__ void mbar_init(uint32_t m, uint32_t c) {
    asm volatile("mbarrier.init.shared.b64 [%0], %1;" :: "r"(m), "r"(c) : "memory");
}
__device__ __forceinline__ void mbar_expect(uint32_t m, uint32_t bytes) {
    asm volatile("mbarrier.arrive.expect_tx.shared.b64 _, [%0], %1;" :: "r"(m), "r"(bytes) : "memory");
}
__device__ __forceinline__ void mbar_arrive(uint32_t m) {
    asm volatile("mbarrier.arrive.shared.b64 _, [%0];" :: "r"(m) : "memory");
}
__device__ __forceinline__ void mbar_arrive_cluster(uint32_t mbar, uint32_t rank) {
    asm volatile(
        "{\n\t.reg .b32 rr;\n\t"
        "mapa.shared::cluster.u32 rr, %0, %1;\n\t"
        "mbarrier.arrive.shared::cluster.b64 _, [rr];\n\t}"
        :: "r"(mbar), "r"(rank) : "memory");
}
__device__ __forceinline__ void mbar_wait(uint32_t m, uint32_t ph) {
    asm volatile(
        "{\n\t.reg .pred P1;\n\t"
        "LAB_W%=:\n\t"
        "mbarrier.try_wait.parity.acquire.cta.shared::cta.b64 P1, [%0], %1, 0x989680;\n\t"
        "@P1 bra LAB_D%=;\n\t"
        "bra LAB_W%=;\n\t"
        "LAB_D%=:\n\t}"
        :: "r"(m), "r"(ph) : "memory");
}
__device__ __forceinline__ void bulk_cp(uint32_t dst, const void* src, uint32_t bytes, uint32_t mbar) {
    asm volatile(
        "cp.async.bulk.shared::cluster.global.mbarrier::complete_tx::bytes [%0], [%1], %2, [%3];"
        :: "r"(dst), "l"(src), "r"(bytes), "r"(mbar) : "memory");
}
__device__ __forceinline__ void mma_tf32_cg2(uint32_t d, uint64_t a, uint64_t b, uint32_t en) {
    asm volatile(
        "{\n\t.reg .pred p;\n\t"
        "setp.ne.u32 p, %5, 0;\n\t"
        "tcgen05.mma.cta_group::2.kind::tf32 [%0], %1, %2, %3, "
        "{%4, %4, %4, %4, %4, %4, %4, %4}, p;\n\t"
        "}"
        :: "r"(d), "l"(a), "l"(b), "r"(IDESC_TF32_CG2), "r"(0u), "r"(en) : "memory");
}
__device__ __forceinline__ void tc_commit_cg2_mc(uint32_t mbar) {
    asm volatile(
        "tcgen05.commit.cta_group::2.mbarrier::arrive::one.shared::cluster.multicast::cluster.b64 [%0], %1;"
        :: "r"(mbar), "h"((uint16_t)3) : "memory");
}
__device__ __forceinline__ uint64_t make_desc(uint32_t addr) {
    return (uint64_t(2) << 61) | (uint64_t(1) << 46) | (uint64_t(64) << 32) |
           (uint64_t(1) << 16) | ((uint64_t)(addr >> 4) & 0x3FFF);
}
#define TC_FENCE_AFTER()  asm volatile("tcgen05.fence::after_thread_sync;" ::: "memory")
#define TC_FENCE_BEFORE() asm volatile("tcgen05.fence::before_thread_sync;" ::: "memory")
#define TC_WAIT_LD()      asm volatile("tcgen05.wait::ld.sync.aligned;" ::: "memory")
#define CLUSTER_SYNC() do { \
    asm volatile("barrier.cluster.arrive.aligned;" ::: "memory"); \
    asm volatile("barrier.cluster.wait.aligned;" ::: "memory"); } while (0)

#define LDTM_X32(r, addr) \
    asm volatile( \
        "tcgen05.ld.sync.aligned.32x32b.x32.b32 " \
        "{%0, %1, %2, %3, %4, %5, %6, %7, " \
        " %8, %9, %10, %11, %12, %13, %14, %15, " \
        " %16, %17, %18, %19, %20, %21, %22, %23, " \
        " %24, %25, %26, %27, %28, %29, %30, %31}, [%32];" \
        : "=r"((r)[0]),  "=r"((r)[1]),  "=r"((r)[2]),  "=r"((r)[3]), \
          "=r"((r)[4]),  "=r"((r)[5]),  "=r"((r)[6]),  "=r"((r)[7]), \
          "=r"((r)[8]),  "=r"((r)[9]),  "=r"((r)[10]), "=r"((r)[11]), \
          "=r"((r)[12]), "=r"((r)[13]), "=r"((r)[14]), "=r"((r)[15]), \
          "=r"((r)[16]), "=r"((r)[17]), "=r"((r)[18]), "=r"((r)[19]), \
          "=r"((r)[20]), "=r"((r)[21]), "=r"((r)[22]), "=r"((r)[23]), \
          "=r"((r)[24]), "=r"((r)[25]), "=r"((r)[26]), "=r"((r)[27]), \
          "=r"((r)[28]), "=r"((r)[29]), "=r"((r)[30]), "=r"((r)[31]) \
        : "r"(addr))
#else
__device__ __forceinline__ u64 pkfma(u64 a, u64 b, u64 c) {
    u64 d;
    asm("fma.rn.f32x2 %0, %1, %2, %3;" : "=l"(d) : "l"(a), "l"(b), "l"(c));
    return d;
}
__device__ __forceinline__ float2 unpk(u64 v) {
    float2 r;
    asm("mov.b64 {%0, %1}, %2;" : "=f"(r.x), "=f"(r.y) : "l"(v));
    return r;
}
#endif

// ---------------------------------------------------------------------------
// prep: norms, labels, tf32 values into full-tile (A) and half-tile (B, cg2
// split) images, per-tile aux (labels + -0.5*sq).
// ---------------------------------------------------------------------------
__global__ void prep_kernel(const float* __restrict__ emb, const int* __restrict__ lab32) {
    int gtid = blockIdx.x * blockDim.x + threadIdx.x;
    int r = gtid >> 5, lane = gtid & 31;

    const float4 v = ((const float4*)(emb + (size_t)r * DIM))[lane];
    float s = v.x * v.x + v.y * v.y + v.z * v.z + v.w * v.w;
    #pragma unroll
    for (int o = 16; o; o >>= 1) s += __shfl_xor_sync(0xffffffffu, s, o);

    uint4 pk;
    asm("cvt.rna.tf32.f32 %0, %1;" : "=r"(pk.x) : "f"(v.x));
    asm("cvt.rna.tf32.f32 %0, %1;" : "=r"(pk.y) : "f"(v.y));
    asm("cvt.rna.tf32.f32 %0, %1;" : "=r"(pk.z) : "f"(v.z));
    asm("cvt.rna.tf32.f32 %0, %1;" : "=r"(pk.w) : "f"(v.w));

    int tile = r >> 7;
    int rin  = r & 127;
    int k0   = lane * 4;

    {   // full-tile image (A): 16 atom-rows x 4 atom-cols
        uint32_t bo = (uint32_t)(((rin >> 3) + (k0 >> 5) * 16) * 1024 + (rin & 7) * 128 + (k0 & 31) * 4);
        uint32_t sw = bo ^ ((bo >> 3) & 0x70);
        *(uint4*)(g_full + (size_t)tile * FT_BYTES + sw) = pk;
    }
    {   // half-tile image (B): 8 atom-rows x 4 atom-cols
        int hf = rin >> 6;
        int rh = rin & 63;
        uint32_t bo = (uint32_t)(((rh >> 3) + (k0 >> 5) * 8) * 1024 + (rh & 7) * 128 + (k0 & 31) * 4);
        uint32_t sw = bo ^ ((bo >> 3) & 0x70);
        *(uint4*)(g_half + (size_t)(tile * 2 + hf) * HT_BYTES + sw) = pk;
    }

    if (lane == 0) {
        g_sq[r] = s;
        g_aux[tile * 256 + 128 + rin] = __float_as_uint(-0.5f * s);
    }

    if (gtid < N_PTS) {
        int odd_or = 0;
        #pragma unroll
        for (int j = 0; j < 16; j++) odd_or |= lab32[2 * j + 1];
        bool is64 = (odd_or == 0);
        int L = is64 ? lab32[2 * gtid] : lab32[gtid];
        g_lab[gtid] = L;
        g_aux[(gtid >> 7) * 256 + (gtid & 127)] = (unsigned)L;
    }
}

// ---------------------------------------------------------------------------
// main: 64 CTA-pairs (cluster 2) = 32 row-slabs (M=256) x 2 column-halves.
// Warps 0-7: epilogue (64 cols each, proven R13 shape). Warp 8: MMA/GO.
// cg2 tf32, 4 B half-stages (fills lead MMA by 4 tiles), 4 D buffers,
// preloaded aux.
// ---------------------------------------------------------------------------
__global__ void __launch_bounds__(NTHREADS, 1) __cluster_dims__(2, 1, 1)
triplet_main(const float* __restrict__ emb) {
#if TC_OK
    extern __shared__ unsigned char smem[];
    const uint32_t sb = smem_u32(smem);
    const int tid = threadIdx.x, wid = tid >> 5, lid = tid & 31;
    const int rank  = blockIdx.x & 1;
    const int cid   = blockIdx.x >> 1;
    const int half  = cid & 1;
    const int slab  = cid >> 1;
    const int strip = slab * 2 + rank;
    const int tbase = half * 32;

    if (wid == 8) {
        asm volatile("tcgen05.alloc.cta_group::2.sync.aligned.shared::cta.b32 [%0], %1;"
                     :: "r"(sb + TMEMPTR_OFF), "r"(512u) : "memory");
        asm volatile("tcgen05.relinquish_alloc_permit.cta_group::2.sync.aligned;");
    }
    if (tid == 0) {
        mbar_init(sb + MB_A, 1);
        #pragma unroll
        for (int s = 0; s < 4; s++) {
            mbar_init(sb + MB_F(s), 1);
            mbar_init(sb + MB_D(s), 1);
            mbar_init(sb + MB_E(s), 8);
            mbar_init(sb + MB_GO(s), 1);
        }
    }
    __syncthreads();
    CLUSTER_SYNC();   // peer barriers live before cluster arrivals / cg2 commit

    uint32_t tmem;
    asm volatile("ld.shared.b32 %0, [%1];" : "=r"(tmem) : "r"(sb + TMEMPTR_OFF));

    if (tid == 0) {
        // A strip (64KB) + all aux for this half (32KB)
        mbar_expect(sb + MB_A, 98304);
        bulk_cp(sb + A_OFF,         g_full + (size_t)strip * FT_BYTES,         32768, sb + MB_A);
        bulk_cp(sb + A_OFF + 32768, g_full + (size_t)strip * FT_BYTES + 32768, 32768, sb + MB_A);
        bulk_cp(sb + AUX_OFF, (const unsigned char*)g_aux + (size_t)tbase * 1024, 32768, sb + MB_A);
        // 4 B half-stages (this CTA's cg2 half)
        #pragma unroll
        for (int s = 0; s < 4; s++) {
            uint32_t fb = sb + MB_F(s);
            mbar_expect(fb, 32768);
            bulk_cp(sb + B_OFF(s), g_half + (size_t)((tbase + s) * 2 + rank) * HT_BYTES, 32768, fb);
        }
    }

    if (wid == 8) {
        if (lid == 0) {
            mbar_wait(sb + MB_A, 0);
            if (rank == 0) {
                // ---------------- MMA leader ----------------
                const uint64_t ad = make_desc(sb + A_OFF);
                for (int t = 0; t < 32; t++) {
                    const uint32_t st = t & 3, par = (t >> 2) & 1;
                    mbar_wait(sb + MB_F(st), par);           // local B half
                    mbar_wait(sb + MB_GO(st), par);          // peer ready (F+E)
                    if (t >= 4)
                        mbar_wait(sb + MB_E(st), ((t - 4) >> 2) & 1);
                    const uint64_t bd = make_desc(sb + B_OFF(st));
                    const uint32_t dT = tmem + st * 128;
                    #pragma unroll
                    for (int s = 0; s < 16; s++) {
                        uint32_t aoff = (s & 3) * 2 + (s >> 2) * 1024;  // full-tile cols
                        uint32_t boff = (s & 3) * 2 + (s >> 2) * 512;   // half-tile cols
                        mma_tf32_cg2(dT, ad + aoff, bd + boff, s > 0);
                    }
                    tc_commit_cg2_mc(sb + MB_D(st));
                }
            } else {
                // ---------------- follower: report F+E readiness ----------
                for (int t = 0; t < 32; t++) {
                    const uint32_t st = t & 3, par = (t >> 2) & 1;
                    mbar_wait(sb + MB_F(st), par);
                    if (t >= 4)
                        mbar_wait(sb + MB_E(st), ((t - 4) >> 2) & 1);
                    mbar_arrive_cluster(sb + MB_GO(st), 0);
                }
            }
        }
    } else {
        // ---------------- epilogue warps 0-7 (64 cols each; R13 shape) -------
        const int rloc  = (wid & 3) * 32 + lid;
        const int cbase = (wid >> 2) * 64;
        const int L = g_lab[strip * 128 + rloc];
        float wp = CUDART_INF_F;
        float wn = -CUDART_INF_F;

        for (int t = 0; t < 32; t++) {
            const uint32_t st = t & 3, par = (t >> 2) & 1;
            mbar_wait(sb + MB_D(st), par);   // cg2 commit multicast
            TC_FENCE_AFTER();

            uint32_t dr[64];
            LDTM_X32(dr,      tmem + st * 128 + cbase);
            LDTM_X32(dr + 32, tmem + st * 128 + cbase + 32);

            // refill B stage st with tile t+4 (D-full(t) proves the pair MMA(t)
            // finished reading both halves of stage st)
            if (tid == 0 && t + 4 < 32) {
                const uint32_t fb = sb + MB_F(st);
                mbar_expect(fb, 32768);
                bulk_cp(sb + B_OFF(st),
                        g_half + (size_t)((tbase + t + 4) * 2 + rank) * HT_BYTES, 32768, fb);
            }

            TC_WAIT_LD();
            TC_FENCE_BEFORE();
            if (lid == 0) mbar_arrive(sb + MB_E(st));   // D[st] drained

            const int*   labs = (const int*)(smem + AUX_OFF + t * 1024);
            const float* qs   = (const float*)(smem + AUX_OFF + t * 1024 + 512);

            if ((tbase + t) != strip) {
                #pragma unroll
                for (int i = 0; i < 64; i += 4) {
                    const int j = cbase + i;
                    int4   lb = *(const int4*)(labs + j);
                    float4 q  = *(const float4*)(qs + j);
                    #define PROC2(dvv, lbv, qv) do {                           \
                        float w_ = __uint_as_float(dvv) + (qv);                \
                        if ((lbv) == L) wp = fminf(wp, w_);                    \
                        else            wn = fmaxf(wn, w_);                    \
                    } while (0)
                    PROC2(dr[i + 0], lb.x, q.x);
                    PROC2(dr[i + 1], lb.y, q.y);
                    PROC2(dr[i + 2], lb.z, q.z);
                    PROC2(dr[i + 3], lb.w, q.w);
                    #undef PROC2
                }
            } else {
                const int selfj = rloc;
                #pragma unroll
                for (int i = 0; i < 64; i += 4) {
                    const int j = cbase + i;
                    int4   lb = *(const int4*)(labs + j);
                    float4 q  = *(const float4*)(qs + j);
                    #define PROC(dvv, lbv, qv, jj) do {                        \
                        float w_ = __uint_as_float(dvv) + (qv);                \
                        if ((lbv) == L) {                                      \
                            if ((jj) != selfj) wp = fminf(wp, w_);             \
                        } else wn = fmaxf(wn, w_);                             \
                    } while (0)
                    PROC(dr[i + 0], lb.x, q.x, j + 0);
                    PROC(dr[i + 1], lb.y, q.y, j + 1);
                    PROC(dr[i + 2], lb.z, q.z, j + 2);
                    PROC(dr[i + 3], lb.w, q.w, j + 3);
                    #undef PROC
                }
            }
        }

        float* sWP = (float*)smem;
        float* sWN = sWP + 256;
        sWP[(wid >> 2) * 128 + rloc] = wp;
        sWN[(wid >> 2) * 128 + rloc] = wn;
    }

    __syncthreads();
    if (tid < 128) {
        float* sWP = (float*)smem;
        float* sWN = sWP + 256;
        float p = fminf(sWP[tid], sWP[128 + tid]);
        float n = fmaxf(sWN[tid], sWN[128 + tid]);
        g_wp[half * N_PTS + strip * 128 + tid] = p;
        g_wn[half * N_PTS + strip * 128 + tid] = n;
    }
    __syncthreads();
    if (wid == 8) {
        asm volatile("tcgen05.dealloc.cta_group::2.sync.aligned.b32 %0, %1;"
                     :: "r"(tmem), "r"(512u));
    }
    CLUSTER_SYNC();   // no CTA exits while peer ops may target its SMEM/TMEM
#else
    // ===================== FALLBACK: pkFMA kernel (guarded to 256 threads) ====
    extern __shared__ float smemf[];
    if (threadIdx.x < 256) {
    float* As2 = smemf;
    float* BsA = smemf + 16384;
    float* BsB = smemf + 32768;
    float* sSq = smemf + 49152;
    int*   sLb = (int*)(smemf + 49408);

    const int tid  = threadIdx.x;
    const int row0 = blockIdx.x * BM;
    const int tn   = tid & 15;
    const int tm   = tid >> 4;

    {
        int m  = tid & 63;
        int kq = tid >> 6;
        const float* src = emb + (size_t)(row0 + m) * DIM;
        #pragma unroll
        for (int q = 0; q < 8; q++) {
            int k = kq * 32 + q * 4;
            float4 v = *(const float4*)(src + k);
            float x0 = -2.f * v.x, x1 = -2.f * v.y, x2 = -2.f * v.z, x3 = -2.f * v.w;
            As2[(k + 0) * 128 + 2 * m] = x0; As2[(k + 0) * 128 + 2 * m + 1] = x0;
            As2[(k + 1) * 128 + 2 * m] = x1; As2[(k + 1) * 128 + 2 * m + 1] = x1;
            As2[(k + 2) * 128 + 2 * m] = x2; As2[(k + 2) * 128 + 2 * m + 1] = x2;
            As2[(k + 3) * 128 + 2 * m] = x3; As2[(k + 3) * 128 + 2 * m + 1] = x3;
        }
    }

    const int bn = tid & 127;
    const int kh = tid >> 7;
    {
        const float4* src = (const float4*)(emb + (size_t)bn * DIM + kh * 64);
        #pragma unroll
        for (int q = 0; q < 16; q++) {
            float4 v = src[q];
            int k = kh * 64 + q * 4;
            BsA[(k + 0) * 128 + bn] = v.x; BsA[(k + 1) * 128 + bn] = v.y;
            BsA[(k + 2) * 128 + bn] = v.z; BsA[(k + 3) * 128 + bn] = v.w;
        }
        if (tid < 128) { sSq[tid] = g_sq[tid]; sLb[tid] = g_lab[tid]; }
    }
    __syncthreads();

    int myLab[4];
    #pragma unroll
    for (int mi = 0; mi < 4; mi++) myLab[mi] = g_lab[row0 + tm * 4 + mi];

    float posm[4] = {-CUDART_INF_F, -CUDART_INF_F, -CUDART_INF_F, -CUDART_INF_F};
    float negm[4] = { CUDART_INF_F,  CUDART_INF_F,  CUDART_INF_F,  CUDART_INF_F};

    int cur = 0;
    for (int t = 0; t < NTILES_FB; t++) {
        float4 breg[16];
        float sqr = 0.f; int lbr = 0;
        const bool has = (t + 1 < NTILES_FB);
        if (has) {
            int coln = (t + 1) * BN;
            const float4* src = (const float4*)(emb + (size_t)(coln + bn) * DIM + kh * 64);
            #pragma unroll
            for (int q = 0; q < 16; q++) breg[q] = src[q];
            if (tid < 128) { sqr = g_sq[coln + tid]; lbr = g_lab[coln + tid]; }
        }

        const float* Bc = (cur == 0) ? BsA : BsB;
        const float* sS = sSq + cur * 128;
        const int*   sL = sLb + cur * 128;

        u64 acc[16];
        #pragma unroll
        for (int i = 0; i < 16; i++) acc[i] = 0ull;

        const float* aBase  = As2 + tm * 8;
        const float* bBase0 = Bc + tn * 4;
        const float* bBase1 = Bc + 64 + tn * 4;

        #pragma unroll 16
        for (int k = 0; k < DIM; k++) {
            ulonglong2 a01 = *(const ulonglong2*)(aBase  + k * 128);
            ulonglong2 a23 = *(const ulonglong2*)(aBase  + k * 128 + 4);
            ulonglong2 b01 = *(const ulonglong2*)(bBase0 + k * 128);
            ulonglong2 b23 = *(const ulonglong2*)(bBase1 + k * 128);
            acc[ 0] = pkfma(a01.x, b01.x, acc[ 0]);
            acc[ 1] = pkfma(a01.x, b01.y, acc[ 1]);
            acc[ 2] = pkfma(a01.x, b23.x, acc[ 2]);
            acc[ 3] = pkfma(a01.x, b23.y, acc[ 3]);
            acc[ 4] = pkfma(a01.y, b01.x, acc[ 4]);
            acc[ 5] = pkfma(a01.y, b01.y, acc[ 5]);
            acc[ 6] = pkfma(a01.y, b23.x, acc[ 6]);
            acc[ 7] = pkfma(a01.y, b23.y, acc[ 7]);
            acc[ 8] = pkfma(a23.x, b01.x, acc[ 8]);
            acc[ 9] = pkfma(a23.x, b01.y, acc[ 9]);
            acc[10] = pkfma(a23.x, b23.x, acc[10]);
            acc[11] = pkfma(a23.x, b23.y, acc[11]);
            acc[12] = pkfma(a23.y, b01.x, acc[12]);
            acc[13] = pkfma(a23.y, b01.y, acc[13]);
            acc[14] = pkfma(a23.y, b23.x, acc[14]);
            acc[15] = pkfma(a23.y, b23.y, acc[15]);
        }

        float4 sq0 = *(const float4*)(sS + tn * 4);
        float4 sq1 = *(const float4*)(sS + 64 + tn * 4);
        int4   lb0 = *(const int4*)(sL + tn * 4);
        int4   lb1 = *(const int4*)(sL + 64 + tn * 4);
        const int col0 = t * BN;

        #pragma unroll
        for (int mi = 0; mi < 4; mi++) {
            const int gm = row0 + tm * 4 + mi;
            const int L  = myLab[mi];
            float pm = posm[mi], nm = negm[mi];
            float2 v0 = unpk(acc[mi * 4 + 0]);
            float2 v1 = unpk(acc[mi * 4 + 1]);
            float2 v2 = unpk(acc[mi * 4 + 2]);
            float2 v3 = unpk(acc[mi * 4 + 3]);
            #define ELEM(gval, sqv, lbv, nloc) do {                      \
                float v = (sqv) + (gval);                                \
                int gn = col0 + (nloc);                                  \
                if ((lbv) == L) { if (gn != gm) pm = fmaxf(pm, v); }     \
                else            { nm = fminf(nm, v); }                   \
            } while (0)
            ELEM(v0.x, sq0.x, lb0.x, tn * 4 + 0);
            ELEM(v0.y, sq0.y, lb0.y, tn * 4 + 1);
            ELEM(v1.x, sq0.z, lb0.z, tn * 4 + 2);
            ELEM(v1.y, sq0.w, lb0.w, tn * 4 + 3);
            ELEM(v2.x, sq1.x, lb1.x, 64 + tn * 4 + 0);
            ELEM(v2.y, sq1.y, lb1.y, 64 + tn * 4 + 1);
            ELEM(v3.x, sq1.z, lb1.z, 64 + tn * 4 + 2);
            ELEM(v3.y, sq1.w, lb1.w, 64 + tn * 4 + 3);
            #undef ELEM
            posm[mi] = pm; negm[mi] = nm;
        }

        if (has) {
            float* Bd = (cur == 0) ? BsB : BsA;
            #pragma unroll
            for (int q = 0; q < 16; q++) {
                int k = kh * 64 + q * 4;
                Bd[(k + 0) * 128 + bn] = breg[q].x;
                Bd[(k + 1) * 128 + bn] = breg[q].y;
                Bd[(k + 2) * 128 + bn] = breg[q].z;
                Bd[(k + 3) * 128 + bn] = breg[q].w;
            }
            if (tid < 128) { sSq[(cur ^ 1) * 128 + tid] = sqr; sLb[(cur ^ 1) * 128 + tid] = lbr; }
        }
        __syncthreads();
        cur ^= 1;
    }

    float* redP = As2;
    float* redN = As2 + 1024;
    #pragma unroll
    for (int mi = 0; mi < 4; mi++) {
        redP[tn * 64 + tm * 4 + mi] = posm[mi];
        redN[tn * 64 + tm * 4 + mi] = negm[mi];
    }
    __syncthreads();
    if (tid < 64) {
        float p = -CUDART_INF_F, nn = CUDART_INF_F;
        #pragma unroll
        for (int j = 0; j < 16; j++) {
            p  = fmaxf(p,  redP[j * 64 + tid]);
            nn = fminf(nn, redN[j * 64 + tid]);
        }
        float sqi = g_sq[row0 + tid];
        g_hp[row0 + tid] = sqi + p;
        g_hn[row0 + tid] = sqi + nn;
    }
    } // tid < 256
#endif
}

// ---------------------------------------------------------------------------
__global__ void finalize_kernel(float* __restrict__ out) {
    __shared__ float ss[256];
    __shared__ int   sc[256];
    int tid = threadIdx.x;
    float s = 0.f; int c = 0;
    for (int i = tid; i < N_PTS; i += 256) {
#if TC_OK
        float wp = fminf(g_wp[i], g_wp[N_PTS + i]);
        float wn = fmaxf(g_wn[i], g_wn[N_PTS + i]);
        float sq = g_sq[i];
        float hp = fmaf(-2.f, wp, sq);
        float hn = fmaf(-2.f, wn, sq);
#else
        float hp = g_hp[i], hn = g_hn[i];
#endif
        if (!isinf(hp) && !isinf(hn)) {
            float dp = sqrtf(fmaxf(hp, 1e-12f));
            float dn = sqrtf(fmaxf(hn, 1e-12f));
            s += fmaxf(dp - dn + 0.3f, 1e-6f);
            c++;
        }
    }
    ss[tid] = s; sc[tid] = c;
    __syncthreads();
    for (int o = 128; o; o >>= 1) {
        if (tid < o) { ss[tid] += ss[tid + o]; sc[tid] += sc[tid + o]; }
        __syncthreads();
    }
    if (tid == 0) out[0] = sc[0] ? (ss[0] / (float)sc[0]) : 0.f;
}

// ---------------------------------------------------------------------------
extern "C" void kernel_launch(void* const* d_in, const int* in_sizes, int n_in,
                              void* d_out, int out_size) {
    const float* emb = (const float*)d_in[0];
    const int*   lab = (const int*)d_in[1];

    cudaFuncSetAttribute(triplet_main, cudaFuncAttributeMaxDynamicSharedMemorySize, SMEM_TOTAL);

    prep_kernel<<<1024, 256>>>(emb, lab);
    triplet_main<<<128, NTHREADS, SMEM_TOTAL>>>(emb);
    finalize_kernel<<<1, 256>>>((float*)d_out);
}